// round 8
// baseline (speedup 1.0000x reference)
#include <cuda_runtime.h>
#include <math.h>

#define B_  2
#define S_  2048
#define D_  2048
#define H_  16
#define HD_ 128

// ---------------- scratch (device globals: no allocation allowed) -------------
__device__ float g_Q[(size_t)B_ * H_ * S_ * HD_];   // [B,H,S,hd]
__device__ float g_K[(size_t)B_ * H_ * S_ * HD_];
__device__ float g_V[(size_t)B_ * H_ * S_ * HD_];
__device__ float g_att[(size_t)B_ * S_ * D_];       // [B,S,D] attention output
__device__ float g_cos[S_ * 64];
__device__ float g_sin[S_ * 64];

// ---------------- RoPE tables -------------------------------------------------
// Mimic reference fp32 rounding: angle = fp32(s * fp32(inv_freq)); trig in double.
__global__ void rope_tables_kernel() {
    int idx = blockIdx.x * blockDim.x + threadIdx.x;
    if (idx >= S_ * 64) return;
    int s = idx >> 6, j = idx & 63;
    float invf = (float)(1.0 / pow(10000.0, (double)(2 * j) / 128.0));
    float ang_f = (float)s * invf;
    double ang = (double)ang_f;
    g_cos[idx] = (float)cos(ang);
    g_sin[idx] = (float)sin(ang);
}

// Apply RoPE in place to g_Q and g_K. One thread per (row, j) pair, j in [0,64).
__global__ void rope_apply_kernel() {
    int idx = blockIdx.x * blockDim.x + threadIdx.x;
    const int total = B_ * H_ * S_ * 64;
    float* T = (idx < total) ? g_Q : g_K;
    int p = (idx < total) ? idx : idx - total;
    int j = p & 63;
    int row = p >> 6;                // (b*H + h)*S + s
    int s = row & (S_ - 1);
    size_t base = (size_t)row * HD_ + j;
    float c  = g_cos[(s << 6) + j];
    float sn = g_sin[(s << 6) + j];
    float x0 = T[base];
    float x1 = T[base + 64];
    T[base]      = x0 * c - x1 * sn;
    T[base + 64] = x1 * c + x0 * sn;
}

// ---------------- SGEMM: C[m,n] = sum_k A[m,k] * W[n,k] ----------------------
// M=4096, N=2048, K=2048. 128x128 tile, BK=32, 256 threads, 8x8 micro-tile.
// mode 0: C row-major [M,N].  mode 1: head layout [B,H,S,hd].
#define GBK 32
#define GPAD 132

__global__ void __launch_bounds__(256) sgemm_kernel(
    const float* __restrict__ A, const float* __restrict__ W,
    float* __restrict__ C, int mode)
{
    __shared__ float As[GBK * GPAD];
    __shared__ float Ws[GBK * GPAD];
    const int K = D_;
    int tid = threadIdx.x;
    int tx = tid & 15, ty = tid >> 4;
    int m0 = blockIdx.y * 128, n0 = blockIdx.x * 128;

    float acc[8][8];
#pragma unroll
    for (int i = 0; i < 8; i++)
#pragma unroll
        for (int j = 0; j < 8; j++) acc[i][j] = 0.f;

    const float* Ablk = A + (size_t)m0 * K;
    const float* Wblk = W + (size_t)n0 * K;

    for (int k0 = 0; k0 < K; k0 += GBK) {
#pragma unroll
        for (int r = 0; r < 4; r++) {
            int idx = tid + 256 * r;          // float4 index, 1024 total
            int row = idx >> 3;               // 8 f4 per row (32 floats)
            int col = (idx & 7) << 2;
            float4 a = *(const float4*)(Ablk + (size_t)row * K + k0 + col);
            As[(col + 0) * GPAD + row] = a.x;
            As[(col + 1) * GPAD + row] = a.y;
            As[(col + 2) * GPAD + row] = a.z;
            As[(col + 3) * GPAD + row] = a.w;
            float4 w = *(const float4*)(Wblk + (size_t)row * K + k0 + col);
            Ws[(col + 0) * GPAD + row] = w.x;
            Ws[(col + 1) * GPAD + row] = w.y;
            Ws[(col + 2) * GPAD + row] = w.z;
            Ws[(col + 3) * GPAD + row] = w.w;
        }
        __syncthreads();
#pragma unroll 8
        for (int kk = 0; kk < GBK; kk++) {
            float ra[8], rb[8];
            *(float4*)&ra[0] = *(const float4*)&As[kk * GPAD + ty * 8];
            *(float4*)&ra[4] = *(const float4*)&As[kk * GPAD + ty * 8 + 4];
            *(float4*)&rb[0] = *(const float4*)&Ws[kk * GPAD + tx * 8];
            *(float4*)&rb[4] = *(const float4*)&Ws[kk * GPAD + tx * 8 + 4];
#pragma unroll
            for (int i = 0; i < 8; i++)
#pragma unroll
                for (int j = 0; j < 8; j++)
                    acc[i][j] += ra[i] * rb[j];
        }
        __syncthreads();
    }

#pragma unroll
    for (int i = 0; i < 8; i++) {
        int m = m0 + ty * 8 + i;
#pragma unroll
        for (int j = 0; j < 8; j++) {
            int n = n0 + tx * 8 + j;
            if (mode == 0) {
                C[(size_t)m * D_ + n] = acc[i][j];
            } else {
                int b = m >> 11, s = m & (S_ - 1);
                int h = n >> 7,  d = n & 127;
                C[(((size_t)b * H_ + h) * S_ + s) * HD_ + d] = acc[i][j];
            }
        }
    }
}

// ---------------- Flash attention (fp32) -------------------------------------
// Block: one head, 128 query rows. 256 threads (16x16).
// Per thread: S fragment 8 rows x 4 cols (cols tx+16j), O fragment 8x8 (cols tx+16u).
#define BQ  128
#define BKT 64
// smem: Qs[128][129] | KPs = union(Ks[64][129], Ps[128][65]) | Vs[64][129]
#define QS_FLOATS  (BQ * 129)
#define KPS_FLOATS (BQ * 65)          /* 8320 >= 64*129=8256 */
#define VS_FLOATS  (BKT * 129)
#define ATT_SMEM_BYTES ((QS_FLOATS + KPS_FLOATS + VS_FLOATS) * 4)

__global__ void __launch_bounds__(256) attn_kernel(const int* __restrict__ mask)
{
    extern __shared__ float sm[];
    float* Qs  = sm;
    float* KPs = sm + QS_FLOATS;
    float* Vs  = KPs + KPS_FLOATS;

    int bh = blockIdx.y;               // b*H + h
    int b = bh >> 4, h = bh & 15;
    int q0 = blockIdx.x * BQ;
    int tid = threadIdx.x;
    int tx = tid & 15, ty = tid >> 4;
    const float scale = 0.08838834764831843f;   // 1/sqrt(128)

    const float* Qg = g_Q + (size_t)bh * S_ * HD_ + (size_t)q0 * HD_;
    const float* Kg = g_K + (size_t)bh * S_ * HD_;
    const float* Vg = g_V + (size_t)bh * S_ * HD_;
    const int*   Mg = mask + (size_t)b * S_ * S_ + (size_t)q0 * S_;

    // Load Q tile, pre-scaled. 128x128 floats = 4096 float4, 16 per thread.
#pragma unroll
    for (int r = 0; r < 16; r++) {
        int idx = tid + 256 * r;
        int row = idx >> 5;            // 32 f4 per row
        int col = (idx & 31) << 2;
        float4 v = *(const float4*)(Qg + (size_t)row * HD_ + col);
        float* dst = Qs + row * 129 + col;
        dst[0] = v.x * scale; dst[1] = v.y * scale;
        dst[2] = v.z * scale; dst[3] = v.w * scale;
    }

    float m_run[8], l_run[8], accO[8][8];
#pragma unroll
    for (int i = 0; i < 8; i++) {
        m_run[i] = -INFINITY;
        l_run[i] = 0.f;
#pragma unroll
        for (int u = 0; u < 8; u++) accO[i][u] = 0.f;
    }

    for (int kt = 0; kt < S_; kt += BKT) {
        __syncthreads();               // previous PV reads of KPs/Vs done
        // Load K and V tiles: 64x128 floats = 2048 float4 each, 8 per thread.
#pragma unroll
        for (int r = 0; r < 8; r++) {
            int idx = tid + 256 * r;
            int row = idx >> 5;
            int col = (idx & 31) << 2;
            float4 kv = *(const float4*)(Kg + (size_t)(kt + row) * HD_ + col);
            float* kd = KPs + row * 129 + col;
            kd[0] = kv.x; kd[1] = kv.y; kd[2] = kv.z; kd[3] = kv.w;
            float4 vv = *(const float4*)(Vg + (size_t)(kt + row) * HD_ + col);
            float* vd = Vs + row * 129 + col;
            vd[0] = vv.x; vd[1] = vv.y; vd[2] = vv.z; vd[3] = vv.w;
        }
        __syncthreads();

        // S = (Q*scale) K^T : sv[8][4]
        float sv[8][4];
#pragma unroll
        for (int i = 0; i < 8; i++)
#pragma unroll
            for (int j = 0; j < 4; j++) sv[i][j] = 0.f;
#pragma unroll 4
        for (int d = 0; d < HD_; d++) {
            float qv[8], kv[4];
#pragma unroll
            for (int i = 0; i < 8; i++) qv[i] = Qs[(ty * 8 + i) * 129 + d];
#pragma unroll
            for (int j = 0; j < 4; j++) kv[j] = KPs[(tx + 16 * j) * 129 + d];
#pragma unroll
            for (int i = 0; i < 8; i++)
#pragma unroll
                for (int j = 0; j < 4; j++)
                    sv[i][j] += qv[i] * kv[j];
        }
        // mask (reference: score = -inf where mask==0)
#pragma unroll
        for (int i = 0; i < 8; i++)
#pragma unroll
            for (int j = 0; j < 4; j++)
                if (Mg[(size_t)(ty * 8 + i) * S_ + kt + tx + 16 * j] == 0)
                    sv[i][j] = -1e30f;

        // online softmax; row stats replicated across the 16-lane tx group
#pragma unroll
        for (int i = 0; i < 8; i++) {
            float mx = sv[i][0];
#pragma unroll
            for (int j = 1; j < 4; j++) mx = fmaxf(mx, sv[i][j]);
#pragma unroll
            for (int o = 8; o; o >>= 1)
                mx = fmaxf(mx, __shfl_xor_sync(0xffffffffu, mx, o));
            float mnew = fmaxf(m_run[i], mx);
            float corr = __expf(m_run[i] - mnew);
            m_run[i] = mnew;
            float ls = 0.f;
#pragma unroll
            for (int j = 0; j < 4; j++) {
                float p = __expf(sv[i][j] - mnew);
                sv[i][j] = p;
                ls += p;
            }
#pragma unroll
            for (int o = 8; o; o >>= 1)
                ls += __shfl_xor_sync(0xffffffffu, ls, o);
            l_run[i] = l_run[i] * corr + ls;
#pragma unroll
            for (int u = 0; u < 8; u++) accO[i][u] *= corr;
        }

        __syncthreads();               // all reads of KPs (as K) done
        // stage P into KPs as [128][65]
#pragma unroll
        for (int i = 0; i < 8; i++)
#pragma unroll
            for (int j = 0; j < 4; j++)
                KPs[(ty * 8 + i) * 65 + tx + 16 * j] = sv[i][j];
        __syncthreads();

        // O += P V
#pragma unroll 4
        for (int kk = 0; kk < BKT; kk++) {
            float pv[8], vv[8];
#pragma unroll
            for (int i = 0; i < 8; i++) pv[i] = KPs[(ty * 8 + i) * 65 + kk];
#pragma unroll
            for (int u = 0; u < 8; u++) vv[u] = Vs[kk * 129 + tx + 16 * u];
#pragma unroll
            for (int i = 0; i < 8; i++)
#pragma unroll
                for (int u = 0; u < 8; u++)
                    accO[i][u] += pv[i] * vv[u];
        }
    }

    // normalize + write to [B,S,D] layout
    float* Og = g_att + ((size_t)b * S_ + q0) * D_ + h * HD_;
#pragma unroll
    for (int i = 0; i < 8; i++) {
        float inv = 1.0f / l_run[i];
        int row = ty * 8 + i;
#pragma unroll
        for (int u = 0; u < 8; u++)
            Og[(size_t)row * D_ + tx + 16 * u] = accO[i][u] * inv;
    }
}

// ---------------- launch ------------------------------------------------------
extern "C" void kernel_launch(void* const* d_in, const int* in_sizes, int n_in,
                              void* d_out, int out_size)
{
    const float* query = (const float*)d_in[0];
    const float* key   = (const float*)d_in[1];
    const float* value = (const float*)d_in[2];
    const int*   mask  = (const int*)d_in[3];
    const float* wq    = (const float*)d_in[4];
    const float* wk    = (const float*)d_in[5];
    const float* wv    = (const float*)d_in[6];
    const float* wo    = (const float*)d_in[7];
    float* out = (float*)d_out;

    float *gQ, *gK, *gV, *gA;
    cudaGetSymbolAddress((void**)&gQ, g_Q);
    cudaGetSymbolAddress((void**)&gK, g_K);
    cudaGetSymbolAddress((void**)&gV, g_V);
    cudaGetSymbolAddress((void**)&gA, g_att);

    cudaFuncSetAttribute(attn_kernel,
                         cudaFuncAttributeMaxDynamicSharedMemorySize,
                         ATT_SMEM_BYTES);

    // RoPE tables
    rope_tables_kernel<<<(S_ * 64 + 255) / 256, 256>>>();

    // Projections (write head layout [B,H,S,hd])
    dim3 pg(D_ / 128, (B_ * S_) / 128);     // (16, 32)
    sgemm_kernel<<<pg, 256>>>(query, wq, gQ, 1);
    sgemm_kernel<<<pg, 256>>>(key,   wk, gK, 1);
    sgemm_kernel<<<pg, 256>>>(value, wv, gV, 1);

    // RoPE on Q and K (in place)
    rope_apply_kernel<<<(2 * B_ * H_ * S_ * 64) / 256, 256>>>();

    // Attention
    attn_kernel<<<dim3(S_ / BQ, B_ * H_), 256, ATT_SMEM_BYTES>>>(mask);

    // Output projection (plain [B,S,D] into d_out)
    sgemm_kernel<<<pg, 256>>>(gA, wo, out, 0);
}

// round 9
// speedup vs baseline: 1.2381x; 1.2381x over previous
#include <cuda_runtime.h>
#include <math.h>

#define B_  2
#define S_  2048
#define D_  2048
#define H_  16
#define HD_ 128

// ---------------- scratch (device globals: no allocation allowed) -------------
__device__ float g_Q[(size_t)B_ * H_ * S_ * HD_];   // [B,H,S,hd]
__device__ float g_K[(size_t)B_ * H_ * S_ * HD_];
__device__ float g_V[(size_t)B_ * H_ * S_ * HD_];
__device__ float g_att[(size_t)B_ * S_ * D_];       // [B,S,D] attention output
__device__ float g_cos[S_ * 64];
__device__ float g_sin[S_ * 64];

// ---------------- RoPE tables -------------------------------------------------
__global__ void rope_tables_kernel() {
    int idx = blockIdx.x * blockDim.x + threadIdx.x;
    if (idx >= S_ * 64) return;
    int s = idx >> 6, j = idx & 63;
    float invf = (float)(1.0 / pow(10000.0, (double)(2 * j) / 128.0));
    float ang_f = (float)s * invf;
    double ang = (double)ang_f;
    g_cos[idx] = (float)cos(ang);
    g_sin[idx] = (float)sin(ang);
}

__global__ void rope_apply_kernel() {
    int idx = blockIdx.x * blockDim.x + threadIdx.x;
    const int total = B_ * H_ * S_ * 64;
    float* T = (idx < total) ? g_Q : g_K;
    int p = (idx < total) ? idx : idx - total;
    int j = p & 63;
    int row = p >> 6;                // (b*H + h)*S + s
    int s = row & (S_ - 1);
    size_t base = (size_t)row * HD_ + j;
    float c  = g_cos[(s << 6) + j];
    float sn = g_sin[(s << 6) + j];
    float x0 = T[base];
    float x1 = T[base + 64];
    T[base]      = x0 * c - x1 * sn;
    T[base + 64] = x1 * c + x0 * sn;
}

// ---------------- 3xTF32 tensor-core SGEMM ------------------------------------
// C[m,n] = sum_k A[m,k] * W[n,k].  M=4096, N=2048, K=2048.
// 128x128 block tile, BK=32, 256 threads (8 warps, 2x4), warp tile 64x32.
// Each fp32 value split into tf32 hi + tf32 lo; 3 mma passes per tile:
//   D += Ahi*Bhi + Ahi*Blo + Alo*Bhi   (error ~2^-23, fp32-class accuracy)
// mode 0: C row-major [M,N].  mode 1: head layout [B,H,S,hd].

#define TPAD 36                       // smem row stride (floats), conflict-free
#define TSM  (128 * TPAD)             // one component array: 4608 words
#define SGEMM_SMEM_BYTES (4 * TSM * 4)  // AsH, AsL, WsH, WsL = 73728 bytes

__device__ __forceinline__ void tf32_split(float x, unsigned &h, unsigned &l) {
    asm("cvt.rna.tf32.f32 %0, %1;" : "=r"(h) : "f"(x));
    float lf = x - __uint_as_float(h);    // exact (tf32 subset of fp32)
    asm("cvt.rna.tf32.f32 %0, %1;" : "=r"(l) : "f"(lf));
}

__device__ __forceinline__ void mma_tf32(float* c, const unsigned* a, const unsigned* b) {
    asm volatile(
        "mma.sync.aligned.m16n8k8.row.col.f32.tf32.tf32.f32 "
        "{%0,%1,%2,%3}, {%4,%5,%6,%7}, {%8,%9}, {%0,%1,%2,%3};"
        : "+f"(c[0]), "+f"(c[1]), "+f"(c[2]), "+f"(c[3])
        : "r"(a[0]), "r"(a[1]), "r"(a[2]), "r"(a[3]), "r"(b[0]), "r"(b[1]));
}

__global__ void __launch_bounds__(256) sgemm_tf32_kernel(
    const float* __restrict__ A, const float* __restrict__ W,
    float* __restrict__ C, int mode)
{
    extern __shared__ unsigned smu[];
    unsigned* AsH = smu;
    unsigned* AsL = AsH + TSM;
    unsigned* WsH = AsL + TSM;
    unsigned* WsL = WsH + TSM;

    const int K = D_;
    int tid  = threadIdx.x;
    int lane = tid & 31;
    int warp = tid >> 5;
    int wm = (warp & 1) * 64;          // warp m offset in block tile
    int wn = (warp >> 1) * 32;         // warp n offset
    int gid = lane >> 2, tig = lane & 3;
    int m0 = blockIdx.y * 128, n0 = blockIdx.x * 128;

    const float* Ablk = A + (size_t)m0 * K;
    const float* Wblk = W + (size_t)n0 * K;

    int ldrow = tid >> 3;              // 0..31  (row step 32 over r)
    int ldcol = (tid & 7) << 2;        // 0,4,...,28

    float acc[4][4][4];
#pragma unroll
    for (int mt = 0; mt < 4; mt++)
#pragma unroll
        for (int nt = 0; nt < 4; nt++)
#pragma unroll
            for (int e = 0; e < 4; e++) acc[mt][nt][e] = 0.f;

    // prefetch chunk 0 into registers
    float4 pa[4], pw[4];
#pragma unroll
    for (int r = 0; r < 4; r++) {
        pa[r] = *(const float4*)(Ablk + (size_t)(ldrow + 32 * r) * K + ldcol);
        pw[r] = *(const float4*)(Wblk + (size_t)(ldrow + 32 * r) * K + ldcol);
    }

    const int NCHUNK = K / 32;
    for (int c = 0; c < NCHUNK; c++) {
        // split + store current chunk to smem
#pragma unroll
        for (int r = 0; r < 4; r++) {
            int off = (ldrow + 32 * r) * TPAD + ldcol;
            unsigned h0,h1,h2,h3,l0,l1,l2,l3;
            tf32_split(pa[r].x, h0, l0); tf32_split(pa[r].y, h1, l1);
            tf32_split(pa[r].z, h2, l2); tf32_split(pa[r].w, h3, l3);
            *(uint4*)&AsH[off] = make_uint4(h0,h1,h2,h3);
            *(uint4*)&AsL[off] = make_uint4(l0,l1,l2,l3);
            tf32_split(pw[r].x, h0, l0); tf32_split(pw[r].y, h1, l1);
            tf32_split(pw[r].z, h2, l2); tf32_split(pw[r].w, h3, l3);
            *(uint4*)&WsH[off] = make_uint4(h0,h1,h2,h3);
            *(uint4*)&WsL[off] = make_uint4(l0,l1,l2,l3);
        }
        __syncthreads();

        // prefetch next chunk (overlaps with compute below)
        if (c + 1 < NCHUNK) {
            int kc = (c + 1) * 32;
#pragma unroll
            for (int r = 0; r < 4; r++) {
                pa[r] = *(const float4*)(Ablk + (size_t)(ldrow + 32 * r) * K + kc + ldcol);
                pw[r] = *(const float4*)(Wblk + (size_t)(ldrow + 32 * r) * K + kc + ldcol);
            }
        }

        // compute: 4 k-steps of 8
#pragma unroll
        for (int ks = 0; ks < 4; ks++) {
            int k0 = ks * 8;
            unsigned ah[4][4], al[4][4], bh[4][2], bl[4][2];
#pragma unroll
            for (int mt = 0; mt < 4; mt++) {
                int base = (wm + mt * 16 + gid) * TPAD + k0 + tig;
                ah[mt][0] = AsH[base];
                ah[mt][1] = AsH[base + 8 * TPAD];
                ah[mt][2] = AsH[base + 4];
                ah[mt][3] = AsH[base + 8 * TPAD + 4];
                al[mt][0] = AsL[base];
                al[mt][1] = AsL[base + 8 * TPAD];
                al[mt][2] = AsL[base + 4];
                al[mt][3] = AsL[base + 8 * TPAD + 4];
            }
#pragma unroll
            for (int nt = 0; nt < 4; nt++) {
                int base = (wn + nt * 8 + gid) * TPAD + k0 + tig;
                bh[nt][0] = WsH[base];
                bh[nt][1] = WsH[base + 4];
                bl[nt][0] = WsL[base];
                bl[nt][1] = WsL[base + 4];
            }
#pragma unroll
            for (int mt = 0; mt < 4; mt++)
#pragma unroll
                for (int nt = 0; nt < 4; nt++) {
                    mma_tf32(acc[mt][nt], ah[mt], bh[nt]);
                    mma_tf32(acc[mt][nt], ah[mt], bl[nt]);
                    mma_tf32(acc[mt][nt], al[mt], bh[nt]);
                }
        }
        __syncthreads();
    }

    // epilogue
#pragma unroll
    for (int mt = 0; mt < 4; mt++) {
#pragma unroll
        for (int nt = 0; nt < 4; nt++) {
            int m = m0 + wm + mt * 16 + gid;
            int n = n0 + wn + nt * 8 + 2 * tig;
            float2 v0 = make_float2(acc[mt][nt][0], acc[mt][nt][1]); // row m
            float2 v1 = make_float2(acc[mt][nt][2], acc[mt][nt][3]); // row m+8
            if (mode == 0) {
                *(float2*)&C[(size_t)m * D_ + n]       = v0;
                *(float2*)&C[(size_t)(m + 8) * D_ + n] = v1;
            } else {
                int h = n >> 7, d = n & 127;
                int b = m >> 11, s = m & (S_ - 1);
                *(float2*)&C[(((size_t)b * H_ + h) * S_ + s) * HD_ + d] = v0;
                int m8 = m + 8;
                int b8 = m8 >> 11, s8 = m8 & (S_ - 1);
                *(float2*)&C[(((size_t)b8 * H_ + h) * S_ + s8) * HD_ + d] = v1;
            }
        }
    }
}

// ---------------- Flash attention (fp32) -------------------------------------
#define BQ  128
#define BKT 64
#define QS_FLOATS  (BQ * 129)
#define KPS_FLOATS (BQ * 65)
#define VS_FLOATS  (BKT * 129)
#define ATT_SMEM_BYTES ((QS_FLOATS + KPS_FLOATS + VS_FLOATS) * 4)

__global__ void __launch_bounds__(256) attn_kernel(const int* __restrict__ mask)
{
    extern __shared__ float sm[];
    float* Qs  = sm;
    float* KPs = sm + QS_FLOATS;
    float* Vs  = KPs + KPS_FLOATS;

    int bh = blockIdx.y;               // b*H + h
    int b = bh >> 4, h = bh & 15;
    int q0 = blockIdx.x * BQ;
    int tid = threadIdx.x;
    int tx = tid & 15, ty = tid >> 4;
    const float scale = 0.08838834764831843f;   // 1/sqrt(128)

    const float* Qg = g_Q + (size_t)bh * S_ * HD_ + (size_t)q0 * HD_;
    const float* Kg = g_K + (size_t)bh * S_ * HD_;
    const float* Vg = g_V + (size_t)bh * S_ * HD_;
    const int*   Mg = mask + (size_t)b * S_ * S_ + (size_t)q0 * S_;

#pragma unroll
    for (int r = 0; r < 16; r++) {
        int idx = tid + 256 * r;
        int row = idx >> 5;
        int col = (idx & 31) << 2;
        float4 v = *(const float4*)(Qg + (size_t)row * HD_ + col);
        float* dst = Qs + row * 129 + col;
        dst[0] = v.x * scale; dst[1] = v.y * scale;
        dst[2] = v.z * scale; dst[3] = v.w * scale;
    }

    float m_run[8], l_run[8], accO[8][8];
#pragma unroll
    for (int i = 0; i < 8; i++) {
        m_run[i] = -INFINITY;
        l_run[i] = 0.f;
#pragma unroll
        for (int u = 0; u < 8; u++) accO[i][u] = 0.f;
    }

    for (int kt = 0; kt < S_; kt += BKT) {
        __syncthreads();
#pragma unroll
        for (int r = 0; r < 8; r++) {
            int idx = tid + 256 * r;
            int row = idx >> 5;
            int col = (idx & 31) << 2;
            float4 kv = *(const float4*)(Kg + (size_t)(kt + row) * HD_ + col);
            float* kd = KPs + row * 129 + col;
            kd[0] = kv.x; kd[1] = kv.y; kd[2] = kv.z; kd[3] = kv.w;
            float4 vv = *(const float4*)(Vg + (size_t)(kt + row) * HD_ + col);
            float* vd = Vs + row * 129 + col;
            vd[0] = vv.x; vd[1] = vv.y; vd[2] = vv.z; vd[3] = vv.w;
        }
        __syncthreads();

        float sv[8][4];
#pragma unroll
        for (int i = 0; i < 8; i++)
#pragma unroll
            for (int j = 0; j < 4; j++) sv[i][j] = 0.f;
#pragma unroll 4
        for (int d = 0; d < HD_; d++) {
            float qv[8], kv[4];
#pragma unroll
            for (int i = 0; i < 8; i++) qv[i] = Qs[(ty * 8 + i) * 129 + d];
#pragma unroll
            for (int j = 0; j < 4; j++) kv[j] = KPs[(tx + 16 * j) * 129 + d];
#pragma unroll
            for (int i = 0; i < 8; i++)
#pragma unroll
                for (int j = 0; j < 4; j++)
                    sv[i][j] += qv[i] * kv[j];
        }
#pragma unroll
        for (int i = 0; i < 8; i++)
#pragma unroll
            for (int j = 0; j < 4; j++)
                if (Mg[(size_t)(ty * 8 + i) * S_ + kt + tx + 16 * j] == 0)
                    sv[i][j] = -1e30f;

#pragma unroll
        for (int i = 0; i < 8; i++) {
            float mx = sv[i][0];
#pragma unroll
            for (int j = 1; j < 4; j++) mx = fmaxf(mx, sv[i][j]);
#pragma unroll
            for (int o = 8; o; o >>= 1)
                mx = fmaxf(mx, __shfl_xor_sync(0xffffffffu, mx, o));
            float mnew = fmaxf(m_run[i], mx);
            float corr = __expf(m_run[i] - mnew);
            m_run[i] = mnew;
            float ls = 0.f;
#pragma unroll
            for (int j = 0; j < 4; j++) {
                float p = __expf(sv[i][j] - mnew);
                sv[i][j] = p;
                ls += p;
            }
#pragma unroll
            for (int o = 8; o; o >>= 1)
                ls += __shfl_xor_sync(0xffffffffu, ls, o);
            l_run[i] = l_run[i] * corr + ls;
#pragma unroll
            for (int u = 0; u < 8; u++) accO[i][u] *= corr;
        }

        __syncthreads();
#pragma unroll
        for (int i = 0; i < 8; i++)
#pragma unroll
            for (int j = 0; j < 4; j++)
                KPs[(ty * 8 + i) * 65 + tx + 16 * j] = sv[i][j];
        __syncthreads();

#pragma unroll 4
        for (int kk = 0; kk < BKT; kk++) {
            float pv[8], vv[8];
#pragma unroll
            for (int i = 0; i < 8; i++) pv[i] = KPs[(ty * 8 + i) * 65 + kk];
#pragma unroll
            for (int u = 0; u < 8; u++) vv[u] = Vs[kk * 129 + tx + 16 * u];
#pragma unroll
            for (int i = 0; i < 8; i++)
#pragma unroll
                for (int u = 0; u < 8; u++)
                    accO[i][u] += pv[i] * vv[u];
        }
    }

    float* Og = g_att + ((size_t)b * S_ + q0) * D_ + h * HD_;
#pragma unroll
    for (int i = 0; i < 8; i++) {
        float inv = 1.0f / l_run[i];
        int row = ty * 8 + i;
#pragma unroll
        for (int u = 0; u < 8; u++)
            Og[(size_t)row * D_ + tx + 16 * u] = accO[i][u] * inv;
    }
}

// ---------------- launch ------------------------------------------------------
extern "C" void kernel_launch(void* const* d_in, const int* in_sizes, int n_in,
                              void* d_out, int out_size)
{
    const float* query = (const float*)d_in[0];
    const float* key   = (const float*)d_in[1];
    const float* value = (const float*)d_in[2];
    const int*   mask  = (const int*)d_in[3];
    const float* wq    = (const float*)d_in[4];
    const float* wk    = (const float*)d_in[5];
    const float* wv    = (const float*)d_in[6];
    const float* wo    = (const float*)d_in[7];
    float* out = (float*)d_out;

    float *gQ, *gK, *gV, *gA;
    cudaGetSymbolAddress((void**)&gQ, g_Q);
    cudaGetSymbolAddress((void**)&gK, g_K);
    cudaGetSymbolAddress((void**)&gV, g_V);
    cudaGetSymbolAddress((void**)&gA, g_att);

    cudaFuncSetAttribute(attn_kernel,
                         cudaFuncAttributeMaxDynamicSharedMemorySize,
                         ATT_SMEM_BYTES);
    cudaFuncSetAttribute(sgemm_tf32_kernel,
                         cudaFuncAttributeMaxDynamicSharedMemorySize,
                         SGEMM_SMEM_BYTES);

    // RoPE tables
    rope_tables_kernel<<<(S_ * 64 + 255) / 256, 256>>>();

    // Projections (write head layout [B,H,S,hd])
    dim3 pg(D_ / 128, (B_ * S_) / 128);     // (16, 32)
    sgemm_tf32_kernel<<<pg, 256, SGEMM_SMEM_BYTES>>>(query, wq, gQ, 1);
    sgemm_tf32_kernel<<<pg, 256, SGEMM_SMEM_BYTES>>>(key,   wk, gK, 1);
    sgemm_tf32_kernel<<<pg, 256, SGEMM_SMEM_BYTES>>>(value, wv, gV, 1);

    // RoPE on Q and K (in place)
    rope_apply_kernel<<<(2 * B_ * H_ * S_ * 64) / 256, 256>>>();

    // Attention
    attn_kernel<<<dim3(S_ / BQ, B_ * H_), 256, ATT_SMEM_BYTES>>>(mask);

    // Output projection (plain [B,S,D] into d_out)
    sgemm_tf32_kernel<<<pg, 256, SGEMM_SMEM_BYTES>>>(gA, wo, out, 0);
}

// round 10
// speedup vs baseline: 1.5403x; 1.2442x over previous
#include <cuda_runtime.h>
#include <math.h>

#define B_  2
#define S_  2048
#define D_  2048
#define H_  16
#define HD_ 128

// ---------------- scratch (device globals: no allocation allowed) -------------
__device__ float g_Q[(size_t)B_ * H_ * S_ * HD_];   // [B,H,S,hd]
__device__ float g_K[(size_t)B_ * H_ * S_ * HD_];
__device__ float g_V[(size_t)B_ * H_ * S_ * HD_];
__device__ float g_att[(size_t)B_ * S_ * D_];       // [B,S,D] attention output
__device__ float g_cos[S_ * 64];
__device__ float g_sin[S_ * 64];

// ---------------- RoPE tables -------------------------------------------------
__global__ void rope_tables_kernel() {
    int idx = blockIdx.x * blockDim.x + threadIdx.x;
    if (idx >= S_ * 64) return;
    int s = idx >> 6, j = idx & 63;
    float invf = (float)(1.0 / pow(10000.0, (double)(2 * j) / 128.0));
    float ang_f = (float)s * invf;
    double ang = (double)ang_f;
    g_cos[idx] = (float)cos(ang);
    g_sin[idx] = (float)sin(ang);
}

__global__ void rope_apply_kernel() {
    int idx = blockIdx.x * blockDim.x + threadIdx.x;
    const int total = B_ * H_ * S_ * 64;
    float* T = (idx < total) ? g_Q : g_K;
    int p = (idx < total) ? idx : idx - total;
    int j = p & 63;
    int row = p >> 6;                // (b*H + h)*S + s
    int s = row & (S_ - 1);
    size_t base = (size_t)row * HD_ + j;
    float c  = g_cos[(s << 6) + j];
    float sn = g_sin[(s << 6) + j];
    float x0 = T[base];
    float x1 = T[base + 64];
    T[base]      = x0 * c - x1 * sn;
    T[base + 64] = x1 * c + x0 * sn;
}

// ---------------- shared helpers ----------------------------------------------
__device__ __forceinline__ void tf32_split(float x, unsigned &h, unsigned &l) {
    asm("cvt.rna.tf32.f32 %0, %1;" : "=r"(h) : "f"(x));
    float lf = x - __uint_as_float(h);    // exact (tf32 subset of fp32)
    asm("cvt.rna.tf32.f32 %0, %1;" : "=r"(l) : "f"(lf));
}

__device__ __forceinline__ void mma_tf32(float* c, const unsigned* a, const unsigned* b) {
    asm volatile(
        "mma.sync.aligned.m16n8k8.row.col.f32.tf32.tf32.f32 "
        "{%0,%1,%2,%3}, {%4,%5,%6,%7}, {%8,%9}, {%0,%1,%2,%3};"
        : "+f"(c[0]), "+f"(c[1]), "+f"(c[2]), "+f"(c[3])
        : "r"(a[0]), "r"(a[1]), "r"(a[2]), "r"(a[3]), "r"(b[0]), "r"(b[1]));
}

// ---------------- 3xTF32 tensor-core SGEMM ------------------------------------
#define TPAD 36
#define TSM  (128 * TPAD)
#define SGEMM_SMEM_BYTES (4 * TSM * 4)

__global__ void __launch_bounds__(256) sgemm_tf32_kernel(
    const float* __restrict__ A, const float* __restrict__ W,
    float* __restrict__ C, int mode)
{
    extern __shared__ unsigned smu[];
    unsigned* AsH = smu;
    unsigned* AsL = AsH + TSM;
    unsigned* WsH = AsL + TSM;
    unsigned* WsL = WsH + TSM;

    const int K = D_;
    int tid  = threadIdx.x;
    int lane = tid & 31;
    int warp = tid >> 5;
    int wm = (warp & 1) * 64;
    int wn = (warp >> 1) * 32;
    int gid = lane >> 2, tig = lane & 3;
    int m0 = blockIdx.y * 128, n0 = blockIdx.x * 128;

    const float* Ablk = A + (size_t)m0 * K;
    const float* Wblk = W + (size_t)n0 * K;

    int ldrow = tid >> 3;
    int ldcol = (tid & 7) << 2;

    float acc[4][4][4];
#pragma unroll
    for (int mt = 0; mt < 4; mt++)
#pragma unroll
        for (int nt = 0; nt < 4; nt++)
#pragma unroll
            for (int e = 0; e < 4; e++) acc[mt][nt][e] = 0.f;

    float4 pa[4], pw[4];
#pragma unroll
    for (int r = 0; r < 4; r++) {
        pa[r] = *(const float4*)(Ablk + (size_t)(ldrow + 32 * r) * K + ldcol);
        pw[r] = *(const float4*)(Wblk + (size_t)(ldrow + 32 * r) * K + ldcol);
    }

    const int NCHUNK = K / 32;
    for (int c = 0; c < NCHUNK; c++) {
#pragma unroll
        for (int r = 0; r < 4; r++) {
            int off = (ldrow + 32 * r) * TPAD + ldcol;
            unsigned h0,h1,h2,h3,l0,l1,l2,l3;
            tf32_split(pa[r].x, h0, l0); tf32_split(pa[r].y, h1, l1);
            tf32_split(pa[r].z, h2, l2); tf32_split(pa[r].w, h3, l3);
            *(uint4*)&AsH[off] = make_uint4(h0,h1,h2,h3);
            *(uint4*)&AsL[off] = make_uint4(l0,l1,l2,l3);
            tf32_split(pw[r].x, h0, l0); tf32_split(pw[r].y, h1, l1);
            tf32_split(pw[r].z, h2, l2); tf32_split(pw[r].w, h3, l3);
            *(uint4*)&WsH[off] = make_uint4(h0,h1,h2,h3);
            *(uint4*)&WsL[off] = make_uint4(l0,l1,l2,l3);
        }
        __syncthreads();

        if (c + 1 < NCHUNK) {
            int kc = (c + 1) * 32;
#pragma unroll
            for (int r = 0; r < 4; r++) {
                pa[r] = *(const float4*)(Ablk + (size_t)(ldrow + 32 * r) * K + kc + ldcol);
                pw[r] = *(const float4*)(Wblk + (size_t)(ldrow + 32 * r) * K + kc + ldcol);
            }
        }

#pragma unroll
        for (int ks = 0; ks < 4; ks++) {
            int k0 = ks * 8;
            unsigned ah[4][4], al[4][4], bh[4][2], bl[4][2];
#pragma unroll
            for (int mt = 0; mt < 4; mt++) {
                int base = (wm + mt * 16 + gid) * TPAD + k0 + tig;
                ah[mt][0] = AsH[base];
                ah[mt][1] = AsH[base + 8 * TPAD];
                ah[mt][2] = AsH[base + 4];
                ah[mt][3] = AsH[base + 8 * TPAD + 4];
                al[mt][0] = AsL[base];
                al[mt][1] = AsL[base + 8 * TPAD];
                al[mt][2] = AsL[base + 4];
                al[mt][3] = AsL[base + 8 * TPAD + 4];
            }
#pragma unroll
            for (int nt = 0; nt < 4; nt++) {
                int base = (wn + nt * 8 + gid) * TPAD + k0 + tig;
                bh[nt][0] = WsH[base];
                bh[nt][1] = WsH[base + 4];
                bl[nt][0] = WsL[base];
                bl[nt][1] = WsL[base + 4];
            }
#pragma unroll
            for (int mt = 0; mt < 4; mt++)
#pragma unroll
                for (int nt = 0; nt < 4; nt++) {
                    mma_tf32(acc[mt][nt], ah[mt], bh[nt]);
                    mma_tf32(acc[mt][nt], ah[mt], bl[nt]);
                    mma_tf32(acc[mt][nt], al[mt], bh[nt]);
                }
        }
        __syncthreads();
    }

#pragma unroll
    for (int mt = 0; mt < 4; mt++) {
#pragma unroll
        for (int nt = 0; nt < 4; nt++) {
            int m = m0 + wm + mt * 16 + gid;
            int n = n0 + wn + nt * 8 + 2 * tig;
            float2 v0 = make_float2(acc[mt][nt][0], acc[mt][nt][1]);
            float2 v1 = make_float2(acc[mt][nt][2], acc[mt][nt][3]);
            if (mode == 0) {
                *(float2*)&C[(size_t)m * D_ + n]       = v0;
                *(float2*)&C[(size_t)(m + 8) * D_ + n] = v1;
            } else {
                int h = n >> 7, d = n & 127;
                int b = m >> 11, s = m & (S_ - 1);
                *(float2*)&C[(((size_t)b * H_ + h) * S_ + s) * HD_ + d] = v0;
                int m8 = m + 8;
                int b8 = m8 >> 11, s8 = m8 & (S_ - 1);
                *(float2*)&C[(((size_t)b8 * H_ + h) * S_ + s8) * HD_ + d] = v1;
            }
        }
    }
}

// ---------------- 3xTF32 tensor-core flash attention ---------------------------
// Block: 1 head, 128 q rows, 256 threads (8 warps). Key tiles of 64.
// Warp w owns q rows [w*16, w*16+16): QK warp tile 16x64, PV warp tile 16x128.
// Softmax fully warp-private. K/V split hi/lo at smem store; Q/P split in regs.
//
// smem (words):
//   Qs  fp32 128x132           @0       16896
//   Kh  tf32 64x132 [key][d]   @16896    8448   (aliased by Ps fp32 128x68 = 8704)
//   Kl  tf32 64x132            @25344    8448
//   Vh  tf32 64x136 [key][d]   @33792    8704
//   Vl  tf32 64x136            @42496    8704
//   wflag int[8]               @51200       8
#define AOFF_KH 16896
#define AOFF_KL (16896 + 8448)
#define AOFF_P  16896
#define AOFF_VH 33792
#define AOFF_VL 42496
#define AOFF_FLAG 51200
#define ATT_SMEM_BYTES ((51200 + 8) * 4)

__global__ void __launch_bounds__(256) attn_tc_kernel(const int* __restrict__ mask)
{
    extern __shared__ float sm[];
    float*    Qs  = sm;
    unsigned* Kh  = (unsigned*)(sm + AOFF_KH);
    unsigned* Kl  = (unsigned*)(sm + AOFF_KL);
    unsigned* Vh  = (unsigned*)(sm + AOFF_VH);
    unsigned* Vl  = (unsigned*)(sm + AOFF_VL);
    float*    Ps  = sm + AOFF_P;
    int*    flagp = (int*)(sm + AOFF_FLAG);

    int bh = blockIdx.y;
    int b = bh >> 4, h = bh & 15;
    int q0 = blockIdx.x * 128;
    int tid = threadIdx.x;
    int lane = tid & 31;
    int warp = tid >> 5;
    int gid = lane >> 2, tig = lane & 3;
    int wm = warp * 16;
    const float scale = 0.08838834764831843f;   // 1/sqrt(128)

    const float* Qg = g_Q + (size_t)bh * S_ * HD_ + (size_t)q0 * HD_;
    const float* Kg = g_K + (size_t)bh * S_ * HD_;
    const float* Vg = g_V + (size_t)bh * S_ * HD_;
    const int*   Mg = mask + (size_t)b * S_ * S_ + (size_t)q0 * S_;

    // Load Q tile (pre-scaled fp32) into Qs, stride 132.
#pragma unroll
    for (int r = 0; r < 16; r++) {
        int idx = tid + 256 * r;
        int row = idx >> 5;
        int col = (idx & 31) << 2;
        float4 v = *(const float4*)(Qg + (size_t)row * HD_ + col);
        float* dst = Qs + row * 132 + col;
        dst[0] = v.x * scale; dst[1] = v.y * scale;
        dst[2] = v.z * scale; dst[3] = v.w * scale;
    }

    float m0 = -INFINITY, m1 = -INFINITY, l0 = 0.f, l1 = 0.f;
    float accO[16][4];
#pragma unroll
    for (int nt = 0; nt < 16; nt++)
#pragma unroll
        for (int e = 0; e < 4; e++) accO[nt][e] = 0.f;

    for (int kt = 0; kt < S_; kt += 64) {
        __syncthreads();                       // prior Ps/Vs reads complete
        // load K,V tiles, split hi/lo
        bool ok = true;
#pragma unroll
        for (int r = 0; r < 8; r++) {
            int idx = tid + 256 * r;
            int row = idx >> 5;
            int col = (idx & 31) << 2;
            float4 kv = *(const float4*)(Kg + (size_t)(kt + row) * HD_ + col);
            unsigned h0,h1,h2,h3,l0_,l1_,l2_,l3_;
            tf32_split(kv.x, h0, l0_); tf32_split(kv.y, h1, l1_);
            tf32_split(kv.z, h2, l2_); tf32_split(kv.w, h3, l3_);
            *(uint4*)&Kh[row * 132 + col] = make_uint4(h0,h1,h2,h3);
            *(uint4*)&Kl[row * 132 + col] = make_uint4(l0_,l1_,l2_,l3_);
            float4 vv = *(const float4*)(Vg + (size_t)(kt + row) * HD_ + col);
            tf32_split(vv.x, h0, l0_); tf32_split(vv.y, h1, l1_);
            tf32_split(vv.z, h2, l2_); tf32_split(vv.w, h3, l3_);
            *(uint4*)&Vh[row * 136 + col] = make_uint4(h0,h1,h2,h3);
            *(uint4*)&Vl[row * 136 + col] = make_uint4(l0_,l1_,l2_,l3_);
        }
        // mask tile scan (128 rows x 64 cols ints)
#pragma unroll
        for (int r = 0; r < 8; r++) {
            int idx = tid + 256 * r;
            int mrow = idx >> 4;
            int mc = (idx & 15) << 2;
            int4 mm = *(const int4*)(Mg + (size_t)mrow * S_ + kt + mc);
            ok = ok && (mm.x != 0) && (mm.y != 0) && (mm.z != 0) && (mm.w != 0);
        }
        unsigned bal = __ballot_sync(0xffffffffu, ok);
        if (lane == 0) flagp[warp] = (bal == 0xffffffffu) ? 1 : 0;
        __syncthreads();
        int allones = flagp[0] & flagp[1] & flagp[2] & flagp[3]
                    & flagp[4] & flagp[5] & flagp[6] & flagp[7];

        // ---- S = (Q*scale) K^T  (16x64 per warp) ----
        float sacc[8][4];
#pragma unroll
        for (int nt = 0; nt < 8; nt++)
#pragma unroll
            for (int e = 0; e < 4; e++) sacc[nt][e] = 0.f;

#pragma unroll
        for (int ks = 0; ks < 16; ks++) {
            int k0 = ks * 8;
            const float* qb = Qs + (wm + gid) * 132 + k0 + tig;
            unsigned ah[4], al[4];
            tf32_split(qb[0],          ah[0], al[0]);
            tf32_split(qb[8 * 132],    ah[1], al[1]);
            tf32_split(qb[4],          ah[2], al[2]);
            tf32_split(qb[8 * 132 + 4],ah[3], al[3]);
#pragma unroll
            for (int nt = 0; nt < 8; nt++) {
                const unsigned* kb = Kh + (nt * 8 + gid) * 132 + k0 + tig;
                const unsigned* klb = Kl + (nt * 8 + gid) * 132 + k0 + tig;
                unsigned bh[2] = { kb[0], kb[4] };
                unsigned bl[2] = { klb[0], klb[4] };
                mma_tf32(sacc[nt], ah, bh);
                mma_tf32(sacc[nt], ah, bl);
                mma_tf32(sacc[nt], al, bh);
            }
        }

        if (!allones) {
            const int* M2 = mask + (size_t)b * S_ * S_;
#pragma unroll
            for (int nt = 0; nt < 8; nt++)
#pragma unroll
                for (int v = 0; v < 4; v++) {
                    int row = q0 + wm + gid + ((v >> 1) << 3);
                    int col = kt + nt * 8 + 2 * tig + (v & 1);
                    if (M2[(size_t)row * S_ + col] == 0) sacc[nt][v] = -1e30f;
                }
        }

        // ---- online softmax (rows wm+gid, wm+8+gid; warp-private) ----
        float mx0 = -INFINITY, mx1 = -INFINITY;
#pragma unroll
        for (int nt = 0; nt < 8; nt++) {
            mx0 = fmaxf(mx0, fmaxf(sacc[nt][0], sacc[nt][1]));
            mx1 = fmaxf(mx1, fmaxf(sacc[nt][2], sacc[nt][3]));
        }
        mx0 = fmaxf(mx0, __shfl_xor_sync(0xffffffffu, mx0, 1));
        mx0 = fmaxf(mx0, __shfl_xor_sync(0xffffffffu, mx0, 2));
        mx1 = fmaxf(mx1, __shfl_xor_sync(0xffffffffu, mx1, 1));
        mx1 = fmaxf(mx1, __shfl_xor_sync(0xffffffffu, mx1, 2));
        float mn0 = fmaxf(m0, mx0), mn1 = fmaxf(m1, mx1);
        float c0 = __expf(m0 - mn0), c1 = __expf(m1 - mn1);
        m0 = mn0; m1 = mn1;
        float s0 = 0.f, s1 = 0.f;
#pragma unroll
        for (int nt = 0; nt < 8; nt++) {
            sacc[nt][0] = __expf(sacc[nt][0] - mn0);
            sacc[nt][1] = __expf(sacc[nt][1] - mn0);
            sacc[nt][2] = __expf(sacc[nt][2] - mn1);
            sacc[nt][3] = __expf(sacc[nt][3] - mn1);
            s0 += sacc[nt][0] + sacc[nt][1];
            s1 += sacc[nt][2] + sacc[nt][3];
        }
        s0 += __shfl_xor_sync(0xffffffffu, s0, 1);
        s0 += __shfl_xor_sync(0xffffffffu, s0, 2);
        s1 += __shfl_xor_sync(0xffffffffu, s1, 1);
        s1 += __shfl_xor_sync(0xffffffffu, s1, 2);
        l0 = l0 * c0 + s0;
        l1 = l1 * c1 + s1;
#pragma unroll
        for (int nt = 0; nt < 16; nt++) {
            accO[nt][0] *= c0; accO[nt][1] *= c0;
            accO[nt][2] *= c1; accO[nt][3] *= c1;
        }

        __syncthreads();                       // all warps done reading Kh/Kl
        // stage P (fp32, stride 68) — same-warp produce/consume
#pragma unroll
        for (int nt = 0; nt < 8; nt++) {
            *(float2*)(Ps + (wm + gid) * 68 + nt * 8 + 2 * tig) =
                make_float2(sacc[nt][0], sacc[nt][1]);
            *(float2*)(Ps + (wm + 8 + gid) * 68 + nt * 8 + 2 * tig) =
                make_float2(sacc[nt][2], sacc[nt][3]);
        }
        __syncwarp();

        // ---- O += P V  (16x128 per warp) ----
#pragma unroll
        for (int ks = 0; ks < 8; ks++) {
            int k0 = ks * 8;
            const float* pb = Ps + (wm + gid) * 68 + k0 + tig;
            unsigned ph[4], pl[4];
            tf32_split(pb[0],          ph[0], pl[0]);
            tf32_split(pb[8 * 68],     ph[1], pl[1]);
            tf32_split(pb[4],          ph[2], pl[2]);
            tf32_split(pb[8 * 68 + 4], ph[3], pl[3]);
#pragma unroll
            for (int nt = 0; nt < 16; nt++) {
                const unsigned* vb  = Vh + (k0 + tig) * 136 + nt * 8 + gid;
                const unsigned* vlb = Vl + (k0 + tig) * 136 + nt * 8 + gid;
                unsigned bh[2] = { vb[0],  vb[4 * 136] };
                unsigned bl[2] = { vlb[0], vlb[4 * 136] };
                mma_tf32(accO[nt], ph, bh);
                mma_tf32(accO[nt], pl, bh);
                mma_tf32(accO[nt], ph, bl);
            }
        }
    }

    // normalize + write [B,S,D]
    float inv0 = 1.0f / l0, inv1 = 1.0f / l1;
    float* Og = g_att + ((size_t)b * S_ + q0 + wm + gid) * D_ + h * HD_;
    float* Og8 = Og + 8 * D_;
#pragma unroll
    for (int nt = 0; nt < 16; nt++) {
        *(float2*)(Og + nt * 8 + 2 * tig) =
            make_float2(accO[nt][0] * inv0, accO[nt][1] * inv0);
        *(float2*)(Og8 + nt * 8 + 2 * tig) =
            make_float2(accO[nt][2] * inv1, accO[nt][3] * inv1);
    }
}

// ---------------- launch ------------------------------------------------------
extern "C" void kernel_launch(void* const* d_in, const int* in_sizes, int n_in,
                              void* d_out, int out_size)
{
    const float* query = (const float*)d_in[0];
    const float* key   = (const float*)d_in[1];
    const float* value = (const float*)d_in[2];
    const int*   mask  = (const int*)d_in[3];
    const float* wq    = (const float*)d_in[4];
    const float* wk    = (const float*)d_in[5];
    const float* wv    = (const float*)d_in[6];
    const float* wo    = (const float*)d_in[7];
    float* out = (float*)d_out;

    float *gQ, *gK, *gV, *gA;
    cudaGetSymbolAddress((void**)&gQ, g_Q);
    cudaGetSymbolAddress((void**)&gK, g_K);
    cudaGetSymbolAddress((void**)&gV, g_V);
    cudaGetSymbolAddress((void**)&gA, g_att);

    cudaFuncSetAttribute(attn_tc_kernel,
                         cudaFuncAttributeMaxDynamicSharedMemorySize,
                         ATT_SMEM_BYTES);
    cudaFuncSetAttribute(sgemm_tf32_kernel,
                         cudaFuncAttributeMaxDynamicSharedMemorySize,
                         SGEMM_SMEM_BYTES);

    // RoPE tables
    rope_tables_kernel<<<(S_ * 64 + 255) / 256, 256>>>();

    // Projections (write head layout [B,H,S,hd])
    dim3 pg(D_ / 128, (B_ * S_) / 128);     // (16, 32)
    sgemm_tf32_kernel<<<pg, 256, SGEMM_SMEM_BYTES>>>(query, wq, gQ, 1);
    sgemm_tf32_kernel<<<pg, 256, SGEMM_SMEM_BYTES>>>(key,   wk, gK, 1);
    sgemm_tf32_kernel<<<pg, 256, SGEMM_SMEM_BYTES>>>(value, wv, gV, 1);

    // RoPE on Q and K (in place)
    rope_apply_kernel<<<(2 * B_ * H_ * S_ * 64) / 256, 256>>>();

    // Attention (tensor-core)
    attn_tc_kernel<<<dim3(S_ / 128, B_ * H_), 256, ATT_SMEM_BYTES>>>(mask);

    // Output projection (plain [B,S,D] into d_out)
    sgemm_tf32_kernel<<<pg, 256, SGEMM_SMEM_BYTES>>>(gA, wo, out, 0);
}

// round 11
// speedup vs baseline: 1.5421x; 1.0011x over previous
#include <cuda_runtime.h>
#include <math.h>

#define B_  2
#define S_  2048
#define D_  2048
#define H_  16
#define HD_ 128

// ---------------- scratch (device globals: no allocation allowed) -------------
__device__ float g_Q[(size_t)B_ * H_ * S_ * HD_];   // [B,H,S,hd]
__device__ float g_K[(size_t)B_ * H_ * S_ * HD_];
__device__ float g_V[(size_t)B_ * H_ * S_ * HD_];
__device__ float g_att[(size_t)B_ * S_ * D_];       // [B,S,D] attention output
__device__ float g_cos[S_ * 64];
__device__ float g_sin[S_ * 64];

// ---------------- RoPE tables -------------------------------------------------
__global__ void rope_tables_kernel() {
    int idx = blockIdx.x * blockDim.x + threadIdx.x;
    if (idx >= S_ * 64) return;
    int s = idx >> 6, j = idx & 63;
    float invf = (float)(1.0 / pow(10000.0, (double)(2 * j) / 128.0));
    float ang_f = (float)s * invf;
    double ang = (double)ang_f;
    g_cos[idx] = (float)cos(ang);
    g_sin[idx] = (float)sin(ang);
}

__global__ void rope_apply_kernel() {
    int idx = blockIdx.x * blockDim.x + threadIdx.x;
    const int total = B_ * H_ * S_ * 64;
    float* T = (idx < total) ? g_Q : g_K;
    int p = (idx < total) ? idx : idx - total;
    int j = p & 63;
    int row = p >> 6;                // (b*H + h)*S + s
    int s = row & (S_ - 1);
    size_t base = (size_t)row * HD_ + j;
    float c  = g_cos[(s << 6) + j];
    float sn = g_sin[(s << 6) + j];
    float x0 = T[base];
    float x1 = T[base + 64];
    T[base]      = x0 * c - x1 * sn;
    T[base + 64] = x1 * c + x0 * sn;
}

// ---------------- shared helpers ----------------------------------------------
__device__ __forceinline__ void tf32_split(float x, unsigned &h, unsigned &l) {
    asm("cvt.rna.tf32.f32 %0, %1;" : "=r"(h) : "f"(x));
    float lf = x - __uint_as_float(h);    // exact (tf32 subset of fp32)
    asm("cvt.rna.tf32.f32 %0, %1;" : "=r"(l) : "f"(lf));
}

__device__ __forceinline__ void mma_tf32(float* c, const unsigned* a, const unsigned* b) {
    asm volatile(
        "mma.sync.aligned.m16n8k8.row.col.f32.tf32.tf32.f32 "
        "{%0,%1,%2,%3}, {%4,%5,%6,%7}, {%8,%9}, {%0,%1,%2,%3};"
        : "+f"(c[0]), "+f"(c[1]), "+f"(c[2]), "+f"(c[3])
        : "r"(a[0]), "r"(a[1]), "r"(a[2]), "r"(a[3]), "r"(b[0]), "r"(b[1]));
}

// ---------------- 3xTF32 tensor-core SGEMM ------------------------------------
#define TPAD 36
#define TSM  (128 * TPAD)
#define SGEMM_SMEM_BYTES (4 * TSM * 4)

__global__ void __launch_bounds__(256) sgemm_tf32_kernel(
    const float* __restrict__ A, const float* __restrict__ W,
    float* __restrict__ C, int mode)
{
    extern __shared__ unsigned smu[];
    unsigned* AsH = smu;
    unsigned* AsL = AsH + TSM;
    unsigned* WsH = AsL + TSM;
    unsigned* WsL = WsH + TSM;

    const int K = D_;
    int tid  = threadIdx.x;
    int lane = tid & 31;
    int warp = tid >> 5;
    int wm = (warp & 1) * 64;
    int wn = (warp >> 1) * 32;
    int gid = lane >> 2, tig = lane & 3;
    int m0 = blockIdx.y * 128, n0 = blockIdx.x * 128;

    const float* Ablk = A + (size_t)m0 * K;
    const float* Wblk = W + (size_t)n0 * K;

    int ldrow = tid >> 3;
    int ldcol = (tid & 7) << 2;

    float acc[4][4][4];
#pragma unroll
    for (int mt = 0; mt < 4; mt++)
#pragma unroll
        for (int nt = 0; nt < 4; nt++)
#pragma unroll
            for (int e = 0; e < 4; e++) acc[mt][nt][e] = 0.f;

    float4 pa[4], pw[4];
#pragma unroll
    for (int r = 0; r < 4; r++) {
        pa[r] = *(const float4*)(Ablk + (size_t)(ldrow + 32 * r) * K + ldcol);
        pw[r] = *(const float4*)(Wblk + (size_t)(ldrow + 32 * r) * K + ldcol);
    }

    const int NCHUNK = K / 32;
    for (int c = 0; c < NCHUNK; c++) {
#pragma unroll
        for (int r = 0; r < 4; r++) {
            int off = (ldrow + 32 * r) * TPAD + ldcol;
            unsigned h0,h1,h2,h3,l0,l1,l2,l3;
            tf32_split(pa[r].x, h0, l0); tf32_split(pa[r].y, h1, l1);
            tf32_split(pa[r].z, h2, l2); tf32_split(pa[r].w, h3, l3);
            *(uint4*)&AsH[off] = make_uint4(h0,h1,h2,h3);
            *(uint4*)&AsL[off] = make_uint4(l0,l1,l2,l3);
            tf32_split(pw[r].x, h0, l0); tf32_split(pw[r].y, h1, l1);
            tf32_split(pw[r].z, h2, l2); tf32_split(pw[r].w, h3, l3);
            *(uint4*)&WsH[off] = make_uint4(h0,h1,h2,h3);
            *(uint4*)&WsL[off] = make_uint4(l0,l1,l2,l3);
        }
        __syncthreads();

        if (c + 1 < NCHUNK) {
            int kc = (c + 1) * 32;
#pragma unroll
            for (int r = 0; r < 4; r++) {
                pa[r] = *(const float4*)(Ablk + (size_t)(ldrow + 32 * r) * K + kc + ldcol);
                pw[r] = *(const float4*)(Wblk + (size_t)(ldrow + 32 * r) * K + kc + ldcol);
            }
        }

#pragma unroll
        for (int ks = 0; ks < 4; ks++) {
            int k0 = ks * 8;
            unsigned ah[4][4], al[4][4], bh[4][2], bl[4][2];
#pragma unroll
            for (int mt = 0; mt < 4; mt++) {
                int base = (wm + mt * 16 + gid) * TPAD + k0 + tig;
                ah[mt][0] = AsH[base];
                ah[mt][1] = AsH[base + 8 * TPAD];
                ah[mt][2] = AsH[base + 4];
                ah[mt][3] = AsH[base + 8 * TPAD + 4];
                al[mt][0] = AsL[base];
                al[mt][1] = AsL[base + 8 * TPAD];
                al[mt][2] = AsL[base + 4];
                al[mt][3] = AsL[base + 8 * TPAD + 4];
            }
#pragma unroll
            for (int nt = 0; nt < 4; nt++) {
                int base = (wn + nt * 8 + gid) * TPAD + k0 + tig;
                bh[nt][0] = WsH[base];
                bh[nt][1] = WsH[base + 4];
                bl[nt][0] = WsL[base];
                bl[nt][1] = WsL[base + 4];
            }
#pragma unroll
            for (int mt = 0; mt < 4; mt++)
#pragma unroll
                for (int nt = 0; nt < 4; nt++) {
                    mma_tf32(acc[mt][nt], ah[mt], bh[nt]);
                    mma_tf32(acc[mt][nt], ah[mt], bl[nt]);
                    mma_tf32(acc[mt][nt], al[mt], bh[nt]);
                }
        }
        __syncthreads();
    }

#pragma unroll
    for (int mt = 0; mt < 4; mt++) {
#pragma unroll
        for (int nt = 0; nt < 4; nt++) {
            int m = m0 + wm + mt * 16 + gid;
            int n = n0 + wn + nt * 8 + 2 * tig;
            float2 v0 = make_float2(acc[mt][nt][0], acc[mt][nt][1]);
            float2 v1 = make_float2(acc[mt][nt][2], acc[mt][nt][3]);
            if (mode == 0) {
                *(float2*)&C[(size_t)m * D_ + n]       = v0;
                *(float2*)&C[(size_t)(m + 8) * D_ + n] = v1;
            } else {
                int h = n >> 7, d = n & 127;
                int b = m >> 11, s = m & (S_ - 1);
                *(float2*)&C[(((size_t)b * H_ + h) * S_ + s) * HD_ + d] = v0;
                int m8 = m + 8;
                int b8 = m8 >> 11, s8 = m8 & (S_ - 1);
                *(float2*)&C[(((size_t)b8 * H_ + h) * S_ + s8) * HD_ + d] = v1;
            }
        }
    }
}

// ---------------- 3xTF32 tensor-core flash attention ---------------------------
// Block: 1 head, 128 q rows, 256 threads (8 warps). Key tiles of 64.
// Warp w owns q rows [w*16, w*16+16): QK warp tile 16x64, PV warp tile 16x128.
// Softmax fully warp-private. K/V split hi/lo at smem store; Q/P split in regs.
//
// smem (words):
//   Qs  fp32 128x132           @0       16896
//   Kh  tf32 64x132 [key][d]   @16896    8448   (aliased by Ps fp32 128x68 = 8704)
//   Kl  tf32 64x132            @25344    8448
//   Vh  tf32 64x136 [key][d]   @33792    8704
//   Vl  tf32 64x136            @42496    8704
//   wflag int[8]               @51200       8
#define AOFF_KH 16896
#define AOFF_KL (16896 + 8448)
#define AOFF_P  16896
#define AOFF_VH 33792
#define AOFF_VL 42496
#define AOFF_FLAG 51200
#define ATT_SMEM_BYTES ((51200 + 8) * 4)

__global__ void __launch_bounds__(256) attn_tc_kernel(const int* __restrict__ mask)
{
    extern __shared__ float sm[];
    float*    Qs  = sm;
    unsigned* Kh  = (unsigned*)(sm + AOFF_KH);
    unsigned* Kl  = (unsigned*)(sm + AOFF_KL);
    unsigned* Vh  = (unsigned*)(sm + AOFF_VH);
    unsigned* Vl  = (unsigned*)(sm + AOFF_VL);
    float*    Ps  = sm + AOFF_P;
    int*    flagp = (int*)(sm + AOFF_FLAG);

    int bh = blockIdx.y;
    int b = bh >> 4, h = bh & 15;
    int q0 = blockIdx.x * 128;
    int tid = threadIdx.x;
    int lane = tid & 31;
    int warp = tid >> 5;
    int gid = lane >> 2, tig = lane & 3;
    int wm = warp * 16;
    const float scale = 0.08838834764831843f;   // 1/sqrt(128)

    const float* Qg = g_Q + (size_t)bh * S_ * HD_ + (size_t)q0 * HD_;
    const float* Kg = g_K + (size_t)bh * S_ * HD_;
    const float* Vg = g_V + (size_t)bh * S_ * HD_;
    const int*   Mg = mask + (size_t)b * S_ * S_ + (size_t)q0 * S_;

    // Load Q tile (pre-scaled fp32) into Qs, stride 132.
#pragma unroll
    for (int r = 0; r < 16; r++) {
        int idx = tid + 256 * r;
        int row = idx >> 5;
        int col = (idx & 31) << 2;
        float4 v = *(const float4*)(Qg + (size_t)row * HD_ + col);
        float* dst = Qs + row * 132 + col;
        dst[0] = v.x * scale; dst[1] = v.y * scale;
        dst[2] = v.z * scale; dst[3] = v.w * scale;
    }

    float m0 = -INFINITY, m1 = -INFINITY, l0 = 0.f, l1 = 0.f;
    float accO[16][4];
#pragma unroll
    for (int nt = 0; nt < 16; nt++)
#pragma unroll
        for (int e = 0; e < 4; e++) accO[nt][e] = 0.f;

    for (int kt = 0; kt < S_; kt += 64) {
        __syncthreads();                       // prior Ps/Vs reads complete
        // load K,V tiles, split hi/lo
        bool ok = true;
#pragma unroll
        for (int r = 0; r < 8; r++) {
            int idx = tid + 256 * r;
            int row = idx >> 5;
            int col = (idx & 31) << 2;
            float4 kv = *(const float4*)(Kg + (size_t)(kt + row) * HD_ + col);
            unsigned h0,h1,h2,h3,l0_,l1_,l2_,l3_;
            tf32_split(kv.x, h0, l0_); tf32_split(kv.y, h1, l1_);
            tf32_split(kv.z, h2, l2_); tf32_split(kv.w, h3, l3_);
            *(uint4*)&Kh[row * 132 + col] = make_uint4(h0,h1,h2,h3);
            *(uint4*)&Kl[row * 132 + col] = make_uint4(l0_,l1_,l2_,l3_);
            float4 vv = *(const float4*)(Vg + (size_t)(kt + row) * HD_ + col);
            tf32_split(vv.x, h0, l0_); tf32_split(vv.y, h1, l1_);
            tf32_split(vv.z, h2, l2_); tf32_split(vv.w, h3, l3_);
            *(uint4*)&Vh[row * 136 + col] = make_uint4(h0,h1,h2,h3);
            *(uint4*)&Vl[row * 136 + col] = make_uint4(l0_,l1_,l2_,l3_);
        }
        // mask tile scan (128 rows x 64 cols ints)
#pragma unroll
        for (int r = 0; r < 8; r++) {
            int idx = tid + 256 * r;
            int mrow = idx >> 4;
            int mc = (idx & 15) << 2;
            int4 mm = *(const int4*)(Mg + (size_t)mrow * S_ + kt + mc);
            ok = ok && (mm.x != 0) && (mm.y != 0) && (mm.z != 0) && (mm.w != 0);
        }
        unsigned bal = __ballot_sync(0xffffffffu, ok);
        if (lane == 0) flagp[warp] = (bal == 0xffffffffu) ? 1 : 0;
        __syncthreads();
        int allones = flagp[0] & flagp[1] & flagp[2] & flagp[3]
                    & flagp[4] & flagp[5] & flagp[6] & flagp[7];

        // ---- S = (Q*scale) K^T  (16x64 per warp) ----
        float sacc[8][4];
#pragma unroll
        for (int nt = 0; nt < 8; nt++)
#pragma unroll
            for (int e = 0; e < 4; e++) sacc[nt][e] = 0.f;

#pragma unroll
        for (int ks = 0; ks < 16; ks++) {
            int k0 = ks * 8;
            const float* qb = Qs + (wm + gid) * 132 + k0 + tig;
            unsigned ah[4], al[4];
            tf32_split(qb[0],          ah[0], al[0]);
            tf32_split(qb[8 * 132],    ah[1], al[1]);
            tf32_split(qb[4],          ah[2], al[2]);
            tf32_split(qb[8 * 132 + 4],ah[3], al[3]);
#pragma unroll
            for (int nt = 0; nt < 8; nt++) {
                const unsigned* kb = Kh + (nt * 8 + gid) * 132 + k0 + tig;
                const unsigned* klb = Kl + (nt * 8 + gid) * 132 + k0 + tig;
                unsigned bh[2] = { kb[0], kb[4] };
                unsigned bl[2] = { klb[0], klb[4] };
                mma_tf32(sacc[nt], ah, bh);
                mma_tf32(sacc[nt], ah, bl);
                mma_tf32(sacc[nt], al, bh);
            }
        }

        if (!allones) {
            const int* M2 = mask + (size_t)b * S_ * S_;
#pragma unroll
            for (int nt = 0; nt < 8; nt++)
#pragma unroll
                for (int v = 0; v < 4; v++) {
                    int row = q0 + wm + gid + ((v >> 1) << 3);
                    int col = kt + nt * 8 + 2 * tig + (v & 1);
                    if (M2[(size_t)row * S_ + col] == 0) sacc[nt][v] = -1e30f;
                }
        }

        // ---- online softmax (rows wm+gid, wm+8+gid; warp-private) ----
        float mx0 = -INFINITY, mx1 = -INFINITY;
#pragma unroll
        for (int nt = 0; nt < 8; nt++) {
            mx0 = fmaxf(mx0, fmaxf(sacc[nt][0], sacc[nt][1]));
            mx1 = fmaxf(mx1, fmaxf(sacc[nt][2], sacc[nt][3]));
        }
        mx0 = fmaxf(mx0, __shfl_xor_sync(0xffffffffu, mx0, 1));
        mx0 = fmaxf(mx0, __shfl_xor_sync(0xffffffffu, mx0, 2));
        mx1 = fmaxf(mx1, __shfl_xor_sync(0xffffffffu, mx1, 1));
        mx1 = fmaxf(mx1, __shfl_xor_sync(0xffffffffu, mx1, 2));
        float mn0 = fmaxf(m0, mx0), mn1 = fmaxf(m1, mx1);
        float c0 = __expf(m0 - mn0), c1 = __expf(m1 - mn1);
        m0 = mn0; m1 = mn1;
        float s0 = 0.f, s1 = 0.f;
#pragma unroll
        for (int nt = 0; nt < 8; nt++) {
            sacc[nt][0] = __expf(sacc[nt][0] - mn0);
            sacc[nt][1] = __expf(sacc[nt][1] - mn0);
            sacc[nt][2] = __expf(sacc[nt][2] - mn1);
            sacc[nt][3] = __expf(sacc[nt][3] - mn1);
            s0 += sacc[nt][0] + sacc[nt][1];
            s1 += sacc[nt][2] + sacc[nt][3];
        }
        s0 += __shfl_xor_sync(0xffffffffu, s0, 1);
        s0 += __shfl_xor_sync(0xffffffffu, s0, 2);
        s1 += __shfl_xor_sync(0xffffffffu, s1, 1);
        s1 += __shfl_xor_sync(0xffffffffu, s1, 2);
        l0 = l0 * c0 + s0;
        l1 = l1 * c1 + s1;
#pragma unroll
        for (int nt = 0; nt < 16; nt++) {
            accO[nt][0] *= c0; accO[nt][1] *= c0;
            accO[nt][2] *= c1; accO[nt][3] *= c1;
        }

        __syncthreads();                       // all warps done reading Kh/Kl
        // stage P (fp32, stride 68) — same-warp produce/consume
#pragma unroll
        for (int nt = 0; nt < 8; nt++) {
            *(float2*)(Ps + (wm + gid) * 68 + nt * 8 + 2 * tig) =
                make_float2(sacc[nt][0], sacc[nt][1]);
            *(float2*)(Ps + (wm + 8 + gid) * 68 + nt * 8 + 2 * tig) =
                make_float2(sacc[nt][2], sacc[nt][3]);
        }
        __syncwarp();

        // ---- O += P V  (16x128 per warp) ----
#pragma unroll
        for (int ks = 0; ks < 8; ks++) {
            int k0 = ks * 8;
            const float* pb = Ps + (wm + gid) * 68 + k0 + tig;
            unsigned ph[4], pl[4];
            tf32_split(pb[0],          ph[0], pl[0]);
            tf32_split(pb[8 * 68],     ph[1], pl[1]);
            tf32_split(pb[4],          ph[2], pl[2]);
            tf32_split(pb[8 * 68 + 4], ph[3], pl[3]);
#pragma unroll
            for (int nt = 0; nt < 16; nt++) {
                const unsigned* vb  = Vh + (k0 + tig) * 136 + nt * 8 + gid;
                const unsigned* vlb = Vl + (k0 + tig) * 136 + nt * 8 + gid;
                unsigned bh[2] = { vb[0],  vb[4 * 136] };
                unsigned bl[2] = { vlb[0], vlb[4 * 136] };
                mma_tf32(accO[nt], ph, bh);
                mma_tf32(accO[nt], pl, bh);
                mma_tf32(accO[nt], ph, bl);
            }
        }
    }

    // normalize + write [B,S,D]
    float inv0 = 1.0f / l0, inv1 = 1.0f / l1;
    float* Og = g_att + ((size_t)b * S_ + q0 + wm + gid) * D_ + h * HD_;
    float* Og8 = Og + 8 * D_;
#pragma unroll
    for (int nt = 0; nt < 16; nt++) {
        *(float2*)(Og + nt * 8 + 2 * tig) =
            make_float2(accO[nt][0] * inv0, accO[nt][1] * inv0);
        *(float2*)(Og8 + nt * 8 + 2 * tig) =
            make_float2(accO[nt][2] * inv1, accO[nt][3] * inv1);
    }
}

// ---------------- launch ------------------------------------------------------
extern "C" void kernel_launch(void* const* d_in, const int* in_sizes, int n_in,
                              void* d_out, int out_size)
{
    const float* query = (const float*)d_in[0];
    const float* key   = (const float*)d_in[1];
    const float* value = (const float*)d_in[2];
    const int*   mask  = (const int*)d_in[3];
    const float* wq    = (const float*)d_in[4];
    const float* wk    = (const float*)d_in[5];
    const float* wv    = (const float*)d_in[6];
    const float* wo    = (const float*)d_in[7];
    float* out = (float*)d_out;

    float *gQ, *gK, *gV, *gA;
    cudaGetSymbolAddress((void**)&gQ, g_Q);
    cudaGetSymbolAddress((void**)&gK, g_K);
    cudaGetSymbolAddress((void**)&gV, g_V);
    cudaGetSymbolAddress((void**)&gA, g_att);

    cudaFuncSetAttribute(attn_tc_kernel,
                         cudaFuncAttributeMaxDynamicSharedMemorySize,
                         ATT_SMEM_BYTES);
    cudaFuncSetAttribute(sgemm_tf32_kernel,
                         cudaFuncAttributeMaxDynamicSharedMemorySize,
                         SGEMM_SMEM_BYTES);

    // RoPE tables
    rope_tables_kernel<<<(S_ * 64 + 255) / 256, 256>>>();

    // Projections (write head layout [B,H,S,hd])
    dim3 pg(D_ / 128, (B_ * S_) / 128);     // (16, 32)
    sgemm_tf32_kernel<<<pg, 256, SGEMM_SMEM_BYTES>>>(query, wq, gQ, 1);
    sgemm_tf32_kernel<<<pg, 256, SGEMM_SMEM_BYTES>>>(key,   wk, gK, 1);
    sgemm_tf32_kernel<<<pg, 256, SGEMM_SMEM_BYTES>>>(value, wv, gV, 1);

    // RoPE on Q and K (in place)
    rope_apply_kernel<<<(2 * B_ * H_ * S_ * 64) / 256, 256>>>();

    // Attention (tensor-core)
    attn_tc_kernel<<<dim3(S_ / 128, B_ * H_), 256, ATT_SMEM_BYTES>>>(mask);

    // Output projection (plain [B,S,D] into d_out)
    sgemm_tf32_kernel<<<pg, 256, SGEMM_SMEM_BYTES>>>(gA, wo, out, 0);
}